// round 2
// baseline (speedup 1.0000x reference)
#include <cuda_runtime.h>

#define B_ 16
#define T_ 24
#define N_ 512
#define D_ 192
#define H_ 6
#define HD_ 32
#define BT_ (B_*T_)          // 384
#define M_ (B_*T_*N_)        // 196608
#define LDB_ (BT_*D_)        // 73728
#define ALPHA_ 0.05f
#define EPS_ 1e-6f

// ---------------- scratch (static device globals; no allocation) -------------
__device__ float g_q  [(size_t)M_ * D_];
__device__ float g_k  [(size_t)M_ * D_];
__device__ float g_v  [(size_t)M_ * D_];
__device__ float g_tx [(size_t)M_ * D_];   // layout [n][b*T+t][d]
__device__ float g_agg[(size_t)M_ * D_];   // layout [n][b*T+t][d]
__device__ float g_anorm[N_ * N_];
__device__ float g_wcomb[D_ * 2 * D_];     // [e][0..191]=alpha*mlp, [e][192..383]=(1-a)*(mlp@fc1)

// ---------------- prep: row-normalized adjacency -----------------------------
__global__ void prep_anorm(const float* __restrict__ adj) {
    int n = blockIdx.x;
    __shared__ float red[128];
    float s = 0.f;
    for (int k = threadIdx.x; k < N_; k += 128) s += adj[n * N_ + k];
    red[threadIdx.x] = s;
    __syncthreads();
    for (int o = 64; o > 0; o >>= 1) {
        if (threadIdx.x < o) red[threadIdx.x] += red[threadIdx.x + o];
        __syncthreads();
    }
    float inv = 1.0f / red[0];
    for (int k = threadIdx.x; k < N_; k += 128) g_anorm[n * N_ + k] = adj[n * N_ + k] * inv;
}

// ---------------- prep: combined weight  Wc[e,c] = sum_f mlp[e,f]*fc1[f,c] ---
__global__ void prep_wcomb(const float* __restrict__ mlp_w, const float* __restrict__ fc1_w) {
    int e = blockIdx.x;     // 192
    int d = threadIdx.x;    // 192
    float acc = 0.f;
    for (int f = 0; f < D_; f++) acc += mlp_w[e * D_ + f] * fc1_w[f * D_ + d];
    g_wcomb[e * (2 * D_) + d]       = ALPHA_ * mlp_w[e * D_ + d];
    g_wcomb[e * (2 * D_) + D_ + d]  = (1.0f - ALPHA_) * acc;
}

// ---------------- GEMM tile config ------------------------------------------
#define BM 128
#define BN 96
#define BK 16
// 256 threads, per-thread 8(m) x 6(n) micro-tile, double-buffered smem

__device__ __forceinline__ void gemm_compute(
    const float (*__restrict__ xs)[BM + 4], const float (*__restrict__ ws)[BN + 4],
    int txm, int tye, float acc[8][6])
{
    #pragma unroll
    for (int kk = 0; kk < BK; kk++) {
        float4 a0 = *(const float4*)&xs[kk][txm * 8];
        float4 a1 = *(const float4*)&xs[kk][txm * 8 + 4];
        float a[8] = {a0.x, a0.y, a0.z, a0.w, a1.x, a1.y, a1.z, a1.w};
        float b[6];
        #pragma unroll
        for (int j = 0; j < 6; j++) b[j] = ws[kk][tye * 6 + j];
        #pragma unroll
        for (int i = 0; i < 8; i++)
            #pragma unroll
            for (int j = 0; j < 6; j++) acc[i][j] = fmaf(a[i], b[j], acc[i][j]);
    }
}

// ---------------- projections: C[m,e] = sum_d A[m,d] * W[e,d]  (NT) ----------
__global__ void __launch_bounds__(256) proj_kernel(
    const float* __restrict__ xq, const float* __restrict__ xk, const float* __restrict__ xv,
    const float* __restrict__ Wq, const float* __restrict__ Wk, const float* __restrict__ Wv)
{
    const float* A; const float* W; float* C;
    if (blockIdx.z == 0)      { A = xq; W = Wq; C = g_q; }
    else if (blockIdx.z == 1) { A = xk; W = Wk; C = g_k; }
    else                      { A = xv; W = Wv; C = g_v; }

    const int m0 = blockIdx.x * BM;
    const int e0 = blockIdx.y * BN;
    __shared__ float xs[2][BK][BM + 4];
    __shared__ float ws[2][BK][BN + 4];
    const int tid = threadIdx.x;
    const int txm = tid & 15, tye = tid >> 4;
    // staging index decomposition (k0-independent)
    const int am0 = tid >> 2,          ak = (tid & 3) * 4;
    const int am1 = (tid + 256) >> 2;                       // A: 512 float4
    const int be0 = tid >> 2,          bk = (tid & 3) * 4;  // B: 384 float4
    const int be1 = be0 + 64;
    float acc[8][6] = {};
    float4 ra0, ra1, rb0, rb1;

    #define PROJ_LOAD(k0) do { \
        ra0 = *(const float4*)&A[(size_t)(m0 + am0) * D_ + (k0) + ak]; \
        ra1 = *(const float4*)&A[(size_t)(m0 + am1) * D_ + (k0) + ak]; \
        rb0 = *(const float4*)&W[(size_t)(e0 + be0) * D_ + (k0) + bk]; \
        if (tid < 128) rb1 = *(const float4*)&W[(size_t)(e0 + be1) * D_ + (k0) + bk]; \
    } while (0)
    #define PROJ_STORE(buf) do { \
        xs[buf][ak + 0][am0] = ra0.x; xs[buf][ak + 1][am0] = ra0.y; \
        xs[buf][ak + 2][am0] = ra0.z; xs[buf][ak + 3][am0] = ra0.w; \
        xs[buf][ak + 0][am1] = ra1.x; xs[buf][ak + 1][am1] = ra1.y; \
        xs[buf][ak + 2][am1] = ra1.z; xs[buf][ak + 3][am1] = ra1.w; \
        ws[buf][bk + 0][be0] = rb0.x; ws[buf][bk + 1][be0] = rb0.y; \
        ws[buf][bk + 2][be0] = rb0.z; ws[buf][bk + 3][be0] = rb0.w; \
        if (tid < 128) { \
            ws[buf][bk + 0][be1] = rb1.x; ws[buf][bk + 1][be1] = rb1.y; \
            ws[buf][bk + 2][be1] = rb1.z; ws[buf][bk + 3][be1] = rb1.w; } \
    } while (0)

    PROJ_LOAD(0); PROJ_STORE(0); __syncthreads();
    int cur = 0;
    for (int k0 = BK; k0 < D_; k0 += BK) {
        PROJ_LOAD(k0);
        gemm_compute(xs[cur], ws[cur], txm, tye, acc);
        PROJ_STORE(cur ^ 1);
        __syncthreads();
        cur ^= 1;
    }
    gemm_compute(xs[cur], ws[cur], txm, tye, acc);
    #undef PROJ_LOAD
    #undef PROJ_STORE

    #pragma unroll
    for (int i = 0; i < 8; i++) {
        int m = m0 + txm * 8 + i;
        #pragma unroll
        for (int j = 0; j < 6; j++)
            C[(size_t)m * D_ + e0 + tye * 6 + j] = acc[i][j];
    }
}

// ---------------- attention + fused RMS norm ---------------------------------
__global__ void __launch_bounds__(192) attn_kernel(
    const float* __restrict__ rms_w, const int* __restrict__ trg_mask)
{
    int n = blockIdx.x, b = blockIdx.y;
    int tid = threadIdx.x;                    // 192 threads
    __shared__ float ks[T_][193];             // reused as output tile later
    __shared__ float vs[T_][193];
    __shared__ float part[T_][8];
    __shared__ float rinv[T_];

    for (int t = 0; t < T_; t++) {
        size_t base = ((size_t)(b * T_ + t) * N_ + n) * D_;
        ks[t][tid] = g_k[base + tid];
        vs[t][tid] = g_v[base + tid];
    }
    int causal = trg_mask ? (trg_mask[0] != 0) : 1;
    __syncthreads();

    float p[T_];
    float inv_sum = 0.f;
    int i = tid % T_, h = tid / T_, hb = h * HD_;
    if (tid < T_ * H_) {
        float qreg[HD_];
        size_t qb = ((size_t)(b * T_ + i) * N_ + n) * D_ + hb;
        #pragma unroll
        for (int d = 0; d < HD_; d++) qreg[d] = g_q[qb + d];

        const float scale = 0.17677669529663687f;   // 1/sqrt(32)
        float mx = -1e30f;
        #pragma unroll
        for (int j = 0; j < T_; j++) {
            float acc = 0.f;
            #pragma unroll
            for (int d = 0; d < HD_; d++) acc += qreg[d] * ks[j][hb + d];
            acc *= scale;
            if (causal && j > i) acc = -1e9f;
            p[j] = acc;
            mx = fmaxf(mx, acc);
        }
        float s = 0.f;
        #pragma unroll
        for (int j = 0; j < T_; j++) { p[j] = expf(p[j] - mx); s += p[j]; }
        inv_sum = 1.0f / s;
    }
    __syncthreads();          // all reads of ks done -> safe to overwrite
    if (tid < T_ * H_) {
        #pragma unroll
        for (int d = 0; d < HD_; d++) {
            float o = 0.f;
            #pragma unroll
            for (int j = 0; j < T_; j++) o += p[j] * vs[j][hb + d];
            ks[i][hb + d] = o * inv_sum;          // ks now holds attn output
        }
    }
    __syncthreads();
    {
        int r = tid >> 3, l = tid & 7;
        float acc = 0.f;
        for (int c = l; c < D_; c += 8) { float x = ks[r][c]; acc += x * x; }
        part[r][l] = acc;
    }
    __syncthreads();
    if (tid < T_) {
        float v = 0.f;
        #pragma unroll
        for (int l = 0; l < 8; l++) v += part[tid][l];
        rinv[tid] = rsqrtf(v * (1.0f / D_) + EPS_);
    }
    __syncthreads();
    float w = rms_w[tid];
    for (int t = 0; t < T_; t++) {
        size_t base = (((size_t)n * B_ + b) * T_ + t) * D_;   // [n][bt][d]
        g_tx[base + tid] = ks[t][tid] * rinv[t] * w;
    }
}

// ---------------- GCN aggregate: C[n,j] = sum_k anorm[n,k] * X[k,j]  (NN) ----
__global__ void __launch_bounds__(256) gcn_kernel() {
    const int j0 = blockIdx.x * BN;
    const int n0 = blockIdx.y * BM;
    __shared__ float as[2][BK][BM + 4];
    __shared__ float bs[2][BK][BN + 4];
    const int tid = threadIdx.x;
    const int txm = tid & 15, tye = tid >> 4;
    const int am0 = tid >> 2,          ak = (tid & 3) * 4;
    const int am1 = (tid + 256) >> 2;
    const int gk0 = tid / 24,          gj0 = (tid % 24) * 4;          // B: 16 x 24 float4
    const int gk1 = (tid + 256) / 24,  gj1 = ((tid + 256) % 24) * 4;
    float acc[8][6] = {};
    float4 ra0, ra1, rb0, rb1;

    #define GCN_LOAD(k0) do { \
        ra0 = *(const float4*)&g_anorm[(n0 + am0) * N_ + (k0) + ak]; \
        ra1 = *(const float4*)&g_anorm[(n0 + am1) * N_ + (k0) + ak]; \
        rb0 = *(const float4*)&g_tx[(size_t)((k0) + gk0) * LDB_ + j0 + gj0]; \
        if (tid < 128) rb1 = *(const float4*)&g_tx[(size_t)((k0) + gk1) * LDB_ + j0 + gj1]; \
    } while (0)
    #define GCN_STORE(buf) do { \
        as[buf][ak + 0][am0] = ra0.x; as[buf][ak + 1][am0] = ra0.y; \
        as[buf][ak + 2][am0] = ra0.z; as[buf][ak + 3][am0] = ra0.w; \
        as[buf][ak + 0][am1] = ra1.x; as[buf][ak + 1][am1] = ra1.y; \
        as[buf][ak + 2][am1] = ra1.z; as[buf][ak + 3][am1] = ra1.w; \
        *(float4*)&bs[buf][gk0][gj0] = rb0; \
        if (tid < 128) *(float4*)&bs[buf][gk1][gj1] = rb1; \
    } while (0)

    GCN_LOAD(0); GCN_STORE(0); __syncthreads();
    int cur = 0;
    for (int k0 = BK; k0 < N_; k0 += BK) {
        GCN_LOAD(k0);
        gemm_compute(as[cur], bs[cur], txm, tye, acc);
        GCN_STORE(cur ^ 1);
        __syncthreads();
        cur ^= 1;
    }
    gemm_compute(as[cur], bs[cur], txm, tye, acc);
    #undef GCN_LOAD
    #undef GCN_STORE

    #pragma unroll
    for (int i = 0; i < 8; i++) {
        int nn = n0 + txm * 8 + i;
        #pragma unroll
        for (int j = 0; j < 6; j++)
            g_agg[(size_t)nn * LDB_ + j0 + tye * 6 + j] = acc[i][j];
    }
}

// ---------------- final: out = [tx | agg] @ wcomb^T + bias  (K=384, NT) ------
__global__ void __launch_bounds__(256) final_kernel(
    const float* __restrict__ mlp_b, float* __restrict__ out)
{
    const int m0 = blockIdx.x * BM;
    const int e0 = blockIdx.y * BN;
    __shared__ float xs[2][BK][BM + 4];
    __shared__ float ws[2][BK][BN + 4];
    const int tid = threadIdx.x;
    const int txm = tid & 15, tye = tid >> 4;
    const int am0 = tid >> 2,          ak = (tid & 3) * 4;
    const int am1 = (tid + 256) >> 2;
    const int be0 = tid >> 2,          bk = (tid & 3) * 4;
    const int be1 = be0 + 64;
    float acc[8][6] = {};
    float4 ra0, ra1, rb0, rb1;

    #define FIN_LOAD(k0) do { \
        const float* Asrc = ((k0) < D_) ? g_tx : g_agg; \
        int kk0 = ((k0) < D_) ? (k0) : ((k0) - D_); \
        ra0 = *(const float4*)&Asrc[(size_t)(m0 + am0) * D_ + kk0 + ak]; \
        ra1 = *(const float4*)&Asrc[(size_t)(m0 + am1) * D_ + kk0 + ak]; \
        rb0 = *(const float4*)&g_wcomb[(e0 + be0) * (2 * D_) + (k0) + bk]; \
        if (tid < 128) rb1 = *(const float4*)&g_wcomb[(e0 + be1) * (2 * D_) + (k0) + bk]; \
    } while (0)
    #define FIN_STORE(buf) do { \
        xs[buf][ak + 0][am0] = ra0.x; xs[buf][ak + 1][am0] = ra0.y; \
        xs[buf][ak + 2][am0] = ra0.z; xs[buf][ak + 3][am0] = ra0.w; \
        xs[buf][ak + 0][am1] = ra1.x; xs[buf][ak + 1][am1] = ra1.y; \
        xs[buf][ak + 2][am1] = ra1.z; xs[buf][ak + 3][am1] = ra1.w; \
        ws[buf][bk + 0][be0] = rb0.x; ws[buf][bk + 1][be0] = rb0.y; \
        ws[buf][bk + 2][be0] = rb0.z; ws[buf][bk + 3][be0] = rb0.w; \
        if (tid < 128) { \
            ws[buf][bk + 0][be1] = rb1.x; ws[buf][bk + 1][be1] = rb1.y; \
            ws[buf][bk + 2][be1] = rb1.z; ws[buf][bk + 3][be1] = rb1.w; } \
    } while (0)

    FIN_LOAD(0); FIN_STORE(0); __syncthreads();
    int cur = 0;
    for (int k0 = BK; k0 < 2 * D_; k0 += BK) {
        FIN_LOAD(k0);
        gemm_compute(xs[cur], ws[cur], txm, tye, acc);
        FIN_STORE(cur ^ 1);
        __syncthreads();
        cur ^= 1;
    }
    gemm_compute(xs[cur], ws[cur], txm, tye, acc);
    #undef FIN_LOAD
    #undef FIN_STORE

    // row m of [n][bt] scratch maps to output [bt][n]
    #pragma unroll
    for (int i = 0; i < 8; i++) {
        int m = m0 + txm * 8 + i;
        int n = m / BT_, bt = m % BT_;
        size_t obase = ((size_t)bt * N_ + n) * D_;
        #pragma unroll
        for (int j = 0; j < 6; j++) {
            int e = e0 + tye * 6 + j;
            out[obase + e] = acc[i][j] + mlp_b[e];
        }
    }
}

// ---------------- launcher ---------------------------------------------------
extern "C" void kernel_launch(void* const* d_in, const int* in_sizes, int n_in,
                              void* d_out, int out_size)
{
    const float* x_q   = (const float*)d_in[0];
    const float* x_k   = (const float*)d_in[1];
    const float* x_v   = (const float*)d_in[2];
    const float* adj   = (const float*)d_in[3];
    const float* Wq    = (const float*)d_in[4];
    const float* Wk    = (const float*)d_in[5];
    const float* Wv    = (const float*)d_in[6];
    const float* rms_w = (const float*)d_in[7];
    const float* fc1_w = (const float*)d_in[8];
    const float* mlp_w = (const float*)d_in[9];
    const float* mlp_b = (const float*)d_in[10];
    const int*   trg   = (n_in > 11) ? (const int*)d_in[11] : nullptr;
    float* out = (float*)d_out;

    prep_anorm<<<N_, 128>>>(adj);
    prep_wcomb<<<D_, D_>>>(mlp_w, fc1_w);
    proj_kernel<<<dim3(M_ / BM, D_ / BN, 3), 256>>>(x_q, x_k, x_v, Wq, Wk, Wv);
    attn_kernel<<<dim3(N_, B_), 192>>>(rms_w, trg);
    gcn_kernel<<<dim3(LDB_ / BN, N_ / BM), 256>>>();
    final_kernel<<<dim3(M_ / BM, D_ / BN), 256>>>(mlp_b, out);
}

// round 4
// speedup vs baseline: 1.0635x; 1.0635x over previous
#include <cuda_runtime.h>

#define B_ 16
#define T_ 24
#define N_ 512
#define D_ 192
#define H_ 6
#define HD_ 32
#define BT_ (B_*T_)          // 384
#define M_ (B_*T_*N_)        // 196608
#define LDB_ (BT_*D_)        // 73728
#define ALPHA_ 0.05f
#define EPS_ 1e-6f

// ---------------- scratch (static device globals; no allocation) -------------
__device__ float g_q  [(size_t)M_ * D_];
__device__ float g_k  [(size_t)M_ * D_];
__device__ float g_v  [(size_t)M_ * D_];
__device__ float g_tx [(size_t)M_ * D_];   // layout [n][b*T+t][d]
__device__ float g_agg[(size_t)M_ * D_];   // layout [n][b*T+t][d]
__device__ float g_anorm[N_ * N_];
__device__ float g_wcomb[D_ * 2 * D_];     // [e][0..191]=alpha*mlp, [e][192..383]=(1-a)*(mlp@fc1)

// ---------------- prep: row-normalized adjacency -----------------------------
__global__ void prep_anorm(const float* __restrict__ adj) {
    int n = blockIdx.x;
    __shared__ float red[128];
    float s = 0.f;
    for (int k = threadIdx.x; k < N_; k += 128) s += adj[n * N_ + k];
    red[threadIdx.x] = s;
    __syncthreads();
    for (int o = 64; o > 0; o >>= 1) {
        if (threadIdx.x < o) red[threadIdx.x] += red[threadIdx.x + o];
        __syncthreads();
    }
    float inv = 1.0f / red[0];
    for (int k = threadIdx.x; k < N_; k += 128) g_anorm[n * N_ + k] = adj[n * N_ + k] * inv;
}

// ---------------- prep: combined weight  Wc[e,c] = sum_f mlp[e,f]*fc1[f,c] ---
__global__ void prep_wcomb(const float* __restrict__ mlp_w, const float* __restrict__ fc1_w) {
    int e = blockIdx.x;     // 192
    int d = threadIdx.x;    // 192
    float acc = 0.f;
    for (int f = 0; f < D_; f++) acc += mlp_w[e * D_ + f] * fc1_w[f * D_ + d];
    g_wcomb[e * (2 * D_) + d]       = ALPHA_ * mlp_w[e * D_ + d];
    g_wcomb[e * (2 * D_) + D_ + d]  = (1.0f - ALPHA_) * acc;
}

// ---------------- GEMM tile config ------------------------------------------
#define BM 128
#define BN 96
#define BK 16
// 256 threads, per-thread 8(m) x 6(n) micro-tile, double-buffered smem.
// Inner product uses packed fma.rn.f32x2: acc pairs along m (contiguous in smem
// -> LDS.64 loads a natural pair), B scalar duplicated via mov.b64 {b,b}.

__device__ __forceinline__ void gemm_compute(
    const float (*__restrict__ xs)[BM + 4], const float (*__restrict__ ws)[BN + 4],
    int txm, int tye, unsigned long long acc[4][6])
{
    #pragma unroll
    for (int kk = 0; kk < BK; kk++) {
        const double* ap = reinterpret_cast<const double*>(&xs[kk][txm * 8]);
        unsigned long long pa[4];
        #pragma unroll
        for (int ip = 0; ip < 4; ip++) pa[ip] = __double_as_longlong(ap[ip]);
        unsigned long long pb[6];
        #pragma unroll
        for (int j = 0; j < 6; j++) {
            float bj = ws[kk][tye * 6 + j];
            asm("mov.b64 %0, {%1, %1};" : "=l"(pb[j]) : "f"(bj));
        }
        #pragma unroll
        for (int j = 0; j < 6; j++)
            #pragma unroll
            for (int ip = 0; ip < 4; ip++)
                asm("fma.rn.f32x2 %0, %1, %2, %0;"
                    : "+l"(acc[ip][j]) : "l"(pa[ip]), "l"(pb[j]));
    }
}

__device__ __forceinline__ float2 unpack2(unsigned long long v) {
    float2 f;
    asm("mov.b64 {%0, %1}, %2;" : "=f"(f.x), "=f"(f.y) : "l"(v));
    return f;
}

// ---------------- projections: C[m,e] = sum_d A[m,d] * W[e,d]  (NT) ----------
__global__ void __launch_bounds__(256) proj_kernel(
    const float* __restrict__ xq, const float* __restrict__ xk, const float* __restrict__ xv,
    const float* __restrict__ Wq, const float* __restrict__ Wk, const float* __restrict__ Wv)
{
    const float* A; const float* W; float* C;
    if (blockIdx.z == 0)      { A = xq; W = Wq; C = g_q; }
    else if (blockIdx.z == 1) { A = xk; W = Wk; C = g_k; }
    else                      { A = xv; W = Wv; C = g_v; }

    const int m0 = blockIdx.x * BM;
    const int e0 = blockIdx.y * BN;
    __shared__ float xs[2][BK][BM + 4];
    __shared__ float ws[2][BK][BN + 4];
    const int tid = threadIdx.x;
    const int txm = tid & 15, tye = tid >> 4;
    const int am0 = tid >> 2,          ak = (tid & 3) * 4;
    const int am1 = (tid + 256) >> 2;                       // A: 512 float4
    const int be0 = tid >> 2,          bk = (tid & 3) * 4;  // B: 384 float4
    const int be1 = be0 + 64;
    unsigned long long acc[4][6] = {};
    float4 ra0, ra1, rb0, rb1;

    #define PROJ_LOAD(k0) do { \
        ra0 = *(const float4*)&A[(size_t)(m0 + am0) * D_ + (k0) + ak]; \
        ra1 = *(const float4*)&A[(size_t)(m0 + am1) * D_ + (k0) + ak]; \
        rb0 = *(const float4*)&W[(size_t)(e0 + be0) * D_ + (k0) + bk]; \
        if (tid < 128) rb1 = *(const float4*)&W[(size_t)(e0 + be1) * D_ + (k0) + bk]; \
    } while (0)
    #define PROJ_STORE(buf) do { \
        xs[buf][ak + 0][am0] = ra0.x; xs[buf][ak + 1][am0] = ra0.y; \
        xs[buf][ak + 2][am0] = ra0.z; xs[buf][ak + 3][am0] = ra0.w; \
        xs[buf][ak + 0][am1] = ra1.x; xs[buf][ak + 1][am1] = ra1.y; \
        xs[buf][ak + 2][am1] = ra1.z; xs[buf][ak + 3][am1] = ra1.w; \
        ws[buf][bk + 0][be0] = rb0.x; ws[buf][bk + 1][be0] = rb0.y; \
        ws[buf][bk + 2][be0] = rb0.z; ws[buf][bk + 3][be0] = rb0.w; \
        if (tid < 128) { \
            ws[buf][bk + 0][be1] = rb1.x; ws[buf][bk + 1][be1] = rb1.y; \
            ws[buf][bk + 2][be1] = rb1.z; ws[buf][bk + 3][be1] = rb1.w; } \
    } while (0)

    PROJ_LOAD(0); PROJ_STORE(0); __syncthreads();
    int cur = 0;
    for (int k0 = BK; k0 < D_; k0 += BK) {
        PROJ_LOAD(k0);
        gemm_compute(xs[cur], ws[cur], txm, tye, acc);
        PROJ_STORE(cur ^ 1);
        __syncthreads();
        cur ^= 1;
    }
    gemm_compute(xs[cur], ws[cur], txm, tye, acc);
    #undef PROJ_LOAD
    #undef PROJ_STORE

    #pragma unroll
    for (int ip = 0; ip < 4; ip++) {
        int m = m0 + txm * 8 + 2 * ip;
        #pragma unroll
        for (int j = 0; j < 6; j++) {
            float2 f = unpack2(acc[ip][j]);
            C[(size_t)m * D_ + e0 + tye * 6 + j]       = f.x;
            C[(size_t)(m + 1) * D_ + e0 + tye * 6 + j] = f.y;
        }
    }
}

// ---------------- attention + fused RMS norm ---------------------------------
#define LDS_ 200   // row stride: 16B-aligned, conflict-free in all phases
__global__ void __launch_bounds__(192) attn_kernel(
    const float* __restrict__ rms_w, const int* __restrict__ trg_mask)
{
    int n = blockIdx.x, b = blockIdx.y;
    int tid = threadIdx.x;                    // 192 threads
    __shared__ float ks[T_][LDS_];            // reused as output tile later
    __shared__ float vs[T_][LDS_];
    __shared__ float part[T_][8];
    __shared__ float rinv[T_];

    for (int t = 0; t < T_; t++) {
        size_t base = ((size_t)(b * T_ + t) * N_ + n) * D_;
        ks[t][tid] = g_k[base + tid];
        vs[t][tid] = g_v[base + tid];
    }
    int causal = trg_mask ? (trg_mask[0] != 0) : 1;
    __syncthreads();

    float p[T_];
    float o4[HD_];
    float inv_sum = 0.f;
    int i = tid % T_, h = tid / T_, hb = h * HD_;
    if (tid < T_ * H_) {
        // Q row in registers (vectorized)
        float4 q4[HD_ / 4];
        size_t qb = ((size_t)(b * T_ + i) * N_ + n) * D_ + hb;
        #pragma unroll
        for (int c = 0; c < HD_ / 4; c++) q4[c] = *(const float4*)&g_q[qb + 4 * c];

        const float scale = 0.17677669529663687f;   // 1/sqrt(32)
        float mx = -1e30f;
        #pragma unroll
        for (int j = 0; j < T_; j++) {
            float acc = 0.f;
            #pragma unroll
            for (int c = 0; c < HD_ / 4; c++) {
                float4 k4 = *(const float4*)&ks[j][hb + 4 * c];
                acc += q4[c].x * k4.x + q4[c].y * k4.y + q4[c].z * k4.z + q4[c].w * k4.w;
            }
            acc *= scale;
            if (causal && j > i) acc = -1e9f;
            p[j] = acc;
            mx = fmaxf(mx, acc);
        }
        float s = 0.f;
        #pragma unroll
        for (int j = 0; j < T_; j++) { p[j] = expf(p[j] - mx); s += p[j]; }
        inv_sum = 1.0f / s;

        // P @ V (vectorized loads of vs)
        #pragma unroll
        for (int c = 0; c < HD_ / 4; c++) {
            float4 o = {0.f, 0.f, 0.f, 0.f};
            #pragma unroll
            for (int j = 0; j < T_; j++) {
                float4 v4 = *(const float4*)&vs[j][hb + 4 * c];
                o.x += p[j] * v4.x; o.y += p[j] * v4.y;
                o.z += p[j] * v4.z; o.w += p[j] * v4.w;
            }
            o4[4 * c + 0] = o.x * inv_sum; o4[4 * c + 1] = o.y * inv_sum;
            o4[4 * c + 2] = o.z * inv_sum; o4[4 * c + 3] = o.w * inv_sum;
        }
    }
    __syncthreads();          // all reads of ks done -> safe to overwrite
    if (tid < T_ * H_) {
        #pragma unroll
        for (int c = 0; c < HD_ / 4; c++)
            *(float4*)&ks[i][hb + 4 * c] =
                make_float4(o4[4*c], o4[4*c+1], o4[4*c+2], o4[4*c+3]);
    }
    __syncthreads();
    // RMS norm over D per row t
    {
        int r = tid >> 3, l = tid & 7;
        float acc = 0.f;
        for (int c = l; c < D_; c += 8) { float x = ks[r][c]; acc += x * x; }
        part[r][l] = acc;
    }
    __syncthreads();
    if (tid < T_) {
        float v = 0.f;
        #pragma unroll
        for (int l = 0; l < 8; l++) v += part[tid][l];
        rinv[tid] = rsqrtf(v * (1.0f / D_) + EPS_);
    }
    __syncthreads();
    float w = rms_w[tid];
    for (int t = 0; t < T_; t++) {
        size_t base = (((size_t)n * B_ + b) * T_ + t) * D_;   // [n][bt][d]
        g_tx[base + tid] = ks[t][tid] * rinv[t] * w;
    }
}

// ---------------- GCN aggregate: C[n,j] = sum_k anorm[n,k] * X[k,j]  (NN) ----
__global__ void __launch_bounds__(256) gcn_kernel() {
    const int j0 = blockIdx.x * BN;
    const int n0 = blockIdx.y * BM;
    __shared__ float as[2][BK][BM + 4];
    __shared__ float bs[2][BK][BN + 4];
    const int tid = threadIdx.x;
    const int txm = tid & 15, tye = tid >> 4;
    const int am0 = tid >> 2,          ak = (tid & 3) * 4;
    const int am1 = (tid + 256) >> 2;
    const int gk0 = tid / 24,          gj0 = (tid % 24) * 4;          // B: 16 x 24 float4
    const int gk1 = (tid + 256) / 24,  gj1 = ((tid + 256) % 24) * 4;
    unsigned long long acc[4][6] = {};
    float4 ra0, ra1, rb0, rb1;

    #define GCN_LOAD(k0) do { \
        ra0 = *(const float4*)&g_anorm[(n0 + am0) * N_ + (k0) + ak]; \
        ra1 = *(const float4*)&g_anorm[(n0 + am1) * N_ + (k0) + ak]; \
        rb0 = *(const float4*)&g_tx[(size_t)((k0) + gk0) * LDB_ + j0 + gj0]; \
        if (tid < 128) rb1 = *(const float4*)&g_tx[(size_t)((k0) + gk1) * LDB_ + j0 + gj1]; \
    } while (0)
    #define GCN_STORE(buf) do { \
        as[buf][ak + 0][am0] = ra0.x; as[buf][ak + 1][am0] = ra0.y; \
        as[buf][ak + 2][am0] = ra0.z; as[buf][ak + 3][am0] = ra0.w; \
        as[buf][ak + 0][am1] = ra1.x; as[buf][ak + 1][am1] = ra1.y; \
        as[buf][ak + 2][am1] = ra1.z; as[buf][ak + 3][am1] = ra1.w; \
        *(float4*)&bs[buf][gk0][gj0] = rb0; \
        if (tid < 128) *(float4*)&bs[buf][gk1][gj1] = rb1; \
    } while (0)

    GCN_LOAD(0); GCN_STORE(0); __syncthreads();
    int cur = 0;
    for (int k0 = BK; k0 < N_; k0 += BK) {
        GCN_LOAD(k0);
        gemm_compute(as[cur], bs[cur], txm, tye, acc);
        GCN_STORE(cur ^ 1);
        __syncthreads();
        cur ^= 1;
    }
    gemm_compute(as[cur], bs[cur], txm, tye, acc);
    #undef GCN_LOAD
    #undef GCN_STORE

    #pragma unroll
    for (int ip = 0; ip < 4; ip++) {
        int nn = n0 + txm * 8 + 2 * ip;
        #pragma unroll
        for (int j = 0; j < 6; j++) {
            float2 f = unpack2(acc[ip][j]);
            g_agg[(size_t)nn * LDB_ + j0 + tye * 6 + j]       = f.x;
            g_agg[(size_t)(nn + 1) * LDB_ + j0 + tye * 6 + j] = f.y;
        }
    }
}

// ---------------- final: out = [tx | agg] @ wcomb^T + bias  (K=384, NT) ------
__global__ void __launch_bounds__(256) final_kernel(
    const float* __restrict__ mlp_b, float* __restrict__ out)
{
    const int m0 = blockIdx.x * BM;
    const int e0 = blockIdx.y * BN;
    __shared__ float xs[2][BK][BM + 4];
    __shared__ float ws[2][BK][BN + 4];
    const int tid = threadIdx.x;
    const int txm = tid & 15, tye = tid >> 4;
    const int am0 = tid >> 2,          ak = (tid & 3) * 4;
    const int am1 = (tid + 256) >> 2;
    const int be0 = tid >> 2,          bk = (tid & 3) * 4;
    const int be1 = be0 + 64;
    unsigned long long acc[4][6] = {};
    float4 ra0, ra1, rb0, rb1;

    #define FIN_LOAD(k0) do { \
        const float* Asrc = ((k0) < D_) ? g_tx : g_agg; \
        int kk0 = ((k0) < D_) ? (k0) : ((k0) - D_); \
        ra0 = *(const float4*)&Asrc[(size_t)(m0 + am0) * D_ + kk0 + ak]; \
        ra1 = *(const float4*)&Asrc[(size_t)(m0 + am1) * D_ + kk0 + ak]; \
        rb0 = *(const float4*)&g_wcomb[(e0 + be0) * (2 * D_) + (k0) + bk]; \
        if (tid < 128) rb1 = *(const float4*)&g_wcomb[(e0 + be1) * (2 * D_) + (k0) + bk]; \
    } while (0)
    #define FIN_STORE(buf) do { \
        xs[buf][ak + 0][am0] = ra0.x; xs[buf][ak + 1][am0] = ra0.y; \
        xs[buf][ak + 2][am0] = ra0.z; xs[buf][ak + 3][am0] = ra0.w; \
        xs[buf][ak + 0][am1] = ra1.x; xs[buf][ak + 1][am1] = ra1.y; \
        xs[buf][ak + 2][am1] = ra1.z; xs[buf][ak + 3][am1] = ra1.w; \
        ws[buf][bk + 0][be0] = rb0.x; ws[buf][bk + 1][be0] = rb0.y; \
        ws[buf][bk + 2][be0] = rb0.z; ws[buf][bk + 3][be0] = rb0.w; \
        if (tid < 128) { \
            ws[buf][bk + 0][be1] = rb1.x; ws[buf][bk + 1][be1] = rb1.y; \
            ws[buf][bk + 2][be1] = rb1.z; ws[buf][bk + 3][be1] = rb1.w; } \
    } while (0)

    FIN_LOAD(0); FIN_STORE(0); __syncthreads();
    int cur = 0;
    for (int k0 = BK; k0 < 2 * D_; k0 += BK) {
        FIN_LOAD(k0);
        gemm_compute(xs[cur], ws[cur], txm, tye, acc);
        FIN_STORE(cur ^ 1);
        __syncthreads();
        cur ^= 1;
    }
    gemm_compute(xs[cur], ws[cur], txm, tye, acc);
    #undef FIN_LOAD
    #undef FIN_STORE

    // row m of [n][bt] scratch maps to output [bt][n]
    #pragma unroll
    for (int ip = 0; ip < 4; ip++) {
        int m = m0 + txm * 8 + 2 * ip;
        #pragma unroll
        for (int j = 0; j < 6; j++) {
            float2 f = unpack2(acc[ip][j]);
            int e = e0 + tye * 6 + j;
            {
                int n = m / BT_, bt = m % BT_;
                out[((size_t)bt * N_ + n) * D_ + e] = f.x + mlp_b[e];
            }
            {
                int n = (m + 1) / BT_, bt = (m + 1) % BT_;
                out[((size_t)bt * N_ + n) * D_ + e] = f.y + mlp_b[e];
            }
        }
    }
}

// ---------------- launcher ---------------------------------------------------
extern "C" void kernel_launch(void* const* d_in, const int* in_sizes, int n_in,
                              void* d_out, int out_size)
{
    const float* x_q   = (const float*)d_in[0];
    const float* x_k   = (const float*)d_in[1];
    const float* x_v   = (const float*)d_in[2];
    const float* adj   = (const float*)d_in[3];
    const float* Wq    = (const float*)d_in[4];
    const float* Wk    = (const float*)d_in[5];
    const float* Wv    = (const float*)d_in[6];
    const float* rms_w = (const float*)d_in[7];
    const float* fc1_w = (const float*)d_in[8];
    const float* mlp_w = (const float*)d_in[9];
    const float* mlp_b = (const float*)d_in[10];
    const int*   trg   = (n_in > 11) ? (const int*)d_in[11] : nullptr;
    float* out = (float*)d_out;

    prep_anorm<<<N_, 128>>>(adj);
    prep_wcomb<<<D_, D_>>>(mlp_w, fc1_w);
    proj_kernel<<<dim3(M_ / BM, D_ / BN, 3), 256>>>(x_q, x_k, x_v, Wq, Wk, Wv);
    attn_kernel<<<dim3(N_, B_), 192>>>(rms_w, trg);
    gcn_kernel<<<dim3(LDB_ / BN, N_ / BM), 256>>>();
    final_kernel<<<dim3(M_ / BM, D_ / BN), 256>>>(mlp_b, out);
}